// round 17
// baseline (speedup 1.0000x reference)
#include <cuda_runtime.h>
#include <cuda_fp16.h>
#include <math.h>
#include <string.h>

#define NODE_DIM 128
#define MAX_NODES 100000

typedef unsigned long long u64;
typedef unsigned int u32;

// Scratch: per-node UV[n] = [u[n]+b1 (128) | v[n] (128)] in fp16, 51.2 MB.
// Columns PERMUTED within each 64-block: p = 16a + 2j + q for c = 2a + 8j + q.
__device__ __align__(16) __half g_UVh[(size_t)MAX_NODES * 256];

// ---------------------------------------------------------------------------
// SMEM layout (dynamic, bytes). A/B rows padded to 136 fp16 (272 B).
// ---------------------------------------------------------------------------
#define KP 136
#define STP 132
#define SM_A 0
#define SM_B 34816
#define SM_STAGE 104448
#define SM_TOTAL (SM_STAGE + 128 * STP * 4)   // 172032

#define LDSM_X4(r0, r1, r2, r3, addr) \
    asm volatile("ldmatrix.sync.aligned.m8n8.x4.shared.b16 {%0,%1,%2,%3}, [%4];" \
                 : "=r"(r0), "=r"(r1), "=r"(r2), "=r"(r3) : "r"(addr))

#define MMA16816F16(c, a, b) \
    asm volatile("mma.sync.aligned.m16n8k16.row.col.f32.f16.f16.f32 " \
                 "{%0,%1,%2,%3}, {%4,%5,%6,%7}, {%8,%9}, {%0,%1,%2,%3};" \
                 : "+f"((c)[0]), "+f"((c)[1]), "+f"((c)[2]), "+f"((c)[3]) \
                 : "r"((a)[0]), "r"((a)[1]), "r"((a)[2]), "r"((a)[3]), \
                   "r"((b)[0]), "r"((b)[1]))

#define CP_ASYNC16(dst, src, srcsz) \
    asm volatile("cp.async.cg.shared.global [%0], [%1], 16, %2;" \
                 :: "r"(dst), "l"(src), "r"(srcsz) : "memory")
#define CP_COMMIT() asm volatile("cp.async.commit_group;" ::: "memory")
#define CP_WAIT0()  asm volatile("cp.async.wait_group 0;" ::: "memory")

__device__ __forceinline__ u32 smem_u32(const void* p) {
    u32 a;
    asm("{ .reg .u64 t; cvta.to.shared.u64 t, %1; cvt.u32.u64 %0, t; }" : "=r"(a) : "l"(p));
    return a;
}
__device__ __forceinline__ u32 h2u(__half2 v) {
    u32 u; memcpy(&u, &v, 4); return u;
}
__device__ __forceinline__ __half2 u2h(u32 u) {
    __half2 h; memcpy(&h, &u, 4); return h;
}
__device__ __forceinline__ u64 h4(float a, float b, float c, float d) {
    return (u64)h2u(__floats2half2_rn(a, b))
         | ((u64)h2u(__floats2half2_rn(c, d)) << 32);
}
__device__ __forceinline__ u32 h2_u32(float a, float b) {
    return h2u(__floats2half2_rn(a, b));
}

// ---------------------------------------------------------------------------
// fp16 GEMM via mma.sync: UV[N,256] = x[N,128] @ Wcat[128,256]
// Single pass, fp16 operands, fp32 accum. A tiles pipelined via cp.async.
// ---------------------------------------------------------------------------
__global__ void __launch_bounds__(256, 1) gemm_mma_kernel(
    const float* __restrict__ x, const float* __restrict__ W1,
    const float* __restrict__ b1, int N)
{
    extern __shared__ char smem[];
    const u32 sb = smem_u32(smem);
    const int tid = threadIdx.x, wid = tid >> 5, lane = tid & 31;

    // ---- B setup (once per CTA): B[n][k] = fp16(Wcat[k][n]) ----
    {
        const int n  = tid;
        const int nc = n & 127;
        const int r0 = (n < 128) ? 0 : 128;
        char* bp = smem + SM_B + n * (KP * 2);
#pragma unroll 4
        for (int k4 = 0; k4 < 32; ++k4) {
            float v0 = W1[(size_t)(r0 + k4 * 4 + 0) * NODE_DIM + nc];
            float v1 = W1[(size_t)(r0 + k4 * 4 + 1) * NODE_DIM + nc];
            float v2 = W1[(size_t)(r0 + k4 * 4 + 2) * NODE_DIM + nc];
            float v3 = W1[(size_t)(r0 + k4 * 4 + 3) * NODE_DIM + nc];
            *(u64*)(bp + k4 * 8) = h4(v0, v1, v2, v3);
        }
    }

    const int m0 = (wid & 1) * 64;
    const int n0 = (wid >> 1) * 64;
    const u32 aOffLane = (u32)(((m0 + (lane & 15)) * KP + ((lane >> 4) & 1) * 8) * 2);
    const u32 bOffLane = (u32)(((n0 + ((lane & 16) ? 8 : 0) + (lane & 7)) * KP
                                + ((lane >> 3) & 1) * 8) * 2);
    const u32 aB = sb + SM_A + aOffLane;
    const u32 bB = sb + SM_B + bOffLane;

    const int aIdx = lane & 3;
    const int cA = n0 + 2 * aIdx;
    float badd[8][2];
#pragma unroll
    for (int j = 0; j < 8; ++j) {
        int c = cA + 8 * j;
        if (c < 128) {
            float2 bv = __ldg((const float2*)&b1[c]);
            badd[j][0] = bv.x; badd[j][1] = bv.y;
        } else {
            badd[j][0] = 0.f; badd[j][1] = 0.f;
        }
    }

    const int tiles = (N + 127) >> 7;

    // ---- Prologue: prefetch first tile ----
    {
        int t0 = blockIdx.x;
        if (t0 < tiles) {
            const int row0 = t0 * 128;
#pragma unroll
            for (int it = 0; it < 16; ++it) {
                int idx = it * 256 + tid;
                int r = idx >> 5, c4 = idx & 31;
                int gr = row0 + r;
                u32 dst = sb + SM_STAGE + (u32)(r * (STP * 4) + c4 * 16);
                const float* src = &x[(size_t)gr * NODE_DIM + c4 * 4];
                CP_ASYNC16(dst, src, (gr < N) ? 16u : 0u);
            }
        }
        CP_COMMIT();
    }

    for (int t = blockIdx.x; t < tiles; t += (int)gridDim.x) {
        const int row0 = t * 128;

        CP_WAIT0();
        __syncthreads();

        // ---- Convert staging f32 -> sA fp16 ----
#pragma unroll 4
        for (int it = 0; it < 16; ++it) {
            int idx = it * 256 + tid;
            int r = idx >> 5, c4 = idx & 31;
            float4 xv = *(const float4*)(smem + SM_STAGE + r * (STP * 4) + c4 * 16);
            u32 off = (u32)(r * (KP * 2) + c4 * 8);
            *(u64*)(smem + SM_A + off) = h4(xv.x, xv.y, xv.z, xv.w);
        }
        __syncthreads();

        // ---- Prefetch next tile ----
        {
            int tn = t + (int)gridDim.x;
            if (tn < tiles) {
                const int rown = tn * 128;
#pragma unroll
                for (int it = 0; it < 16; ++it) {
                    int idx = it * 256 + tid;
                    int r = idx >> 5, c4 = idx & 31;
                    int gr = rown + r;
                    u32 dst = sb + SM_STAGE + (u32)(r * (STP * 4) + c4 * 16);
                    const float* src = &x[(size_t)gr * NODE_DIM + c4 * 4];
                    CP_ASYNC16(dst, src, (gr < N) ? 16u : 0u);
                }
            }
            CP_COMMIT();
        }

        // ---- Mainloop: 8 k-steps, 8 LDSM + 32 MMA each ----
        float acc[4][8][4];
#pragma unroll
        for (int i = 0; i < 4; ++i)
#pragma unroll
            for (int j = 0; j < 8; ++j)
#pragma unroll
                for (int q = 0; q < 4; ++q) acc[i][j][q] = 0.0f;

#pragma unroll
        for (int ks = 0; ks < 8; ++ks) {
            const u32 ko = (u32)(ks * 32);

            u32 a[4][4], b[8][2];
#pragma unroll
            for (int i = 0; i < 4; ++i)
                LDSM_X4(a[i][0], a[i][1], a[i][2], a[i][3],
                        aB + ko + (u32)(i * 16 * KP * 2));
#pragma unroll
            for (int jj = 0; jj < 4; ++jj)
                LDSM_X4(b[2 * jj][0], b[2 * jj][1], b[2 * jj + 1][0], b[2 * jj + 1][1],
                        bB + ko + (u32)(jj * 16 * KP * 2));
#pragma unroll
            for (int i = 0; i < 4; ++i)
#pragma unroll
                for (int j = 0; j < 8; ++j)
                    MMA16816F16(acc[i][j], a[i], b[j]);
        }

        // ---- Epilogue: +b1, fp16, permuted -> 2x STG.128 per row ----
        const int rA = row0 + m0 + (lane >> 2);
        const u32 colBase = (u32)(n0 + 16 * aIdx);
#pragma unroll
        for (int i = 0; i < 4; ++i) {
#pragma unroll
            for (int half = 0; half < 2; ++half) {
                int r = rA + 16 * i + 8 * half;
                if (r < N) {
                    u32 w[8];
#pragma unroll
                    for (int j = 0; j < 8; ++j)
                        w[j] = h2_u32(acc[i][j][2 * half + 0] + badd[j][0],
                                      acc[i][j][2 * half + 1] + badd[j][1]);
                    __half* dst = &g_UVh[(size_t)r * 256 + colBase];
                    *(uint4*)dst = make_uint4(w[0], w[1], w[2], w[3]);
                    *(uint4*)(dst + 8) = make_uint4(w[4], w[5], w[6], w[7]);
                }
            }
        }
    }
}

// ---------------------------------------------------------------------------
// Edge pass: 2 edges per 16-lane group, half2 math, direct leader store.
//   h = hmax2(hadd2(u,v),0); dot via short HFMA2 chains; fp32 group-reduce;
//   leader computes sigmoid (via __expf) and stores both edges directly.
// ---------------------------------------------------------------------------
__global__ void __launch_bounds__(256) edge_kernel(
    const void* __restrict__ ei_raw,
    const float* __restrict__ W2,
    const float* __restrict__ b2,
    float* __restrict__ out, int E, int N)
{
    __shared__ u32 s_w2h[64];

    const int tid  = threadIdx.x;
    const int wid  = tid >> 5;
    const int lane = tid & 31;
    const int grp  = lane >> 4;
    const int gl   = lane & 15;

    if (tid < 64) {
        int blk = tid >> 5, i = tid & 31;
        int c0 = blk * 64 + 2 * (i >> 3) + 8 * (i & 7);
        s_w2h[tid] = h2u(__floats2half2_rn(__ldg(&W2[c0]), __ldg(&W2[c0 + 1])));
    }

    const long long* p64 = (const long long*)ei_raw;
    long long probe = __ldg(&p64[lane & 15]);
    bool okp = (probe >= 0 && probe < (long long)N);
    bool is64 = (__ballot_sync(0xffffffffu, okp) == 0xffffffffu);

    __syncthreads();

    const long long e0 = (long long)blockIdx.x * 32;
    const int gidx = wid * 2 + grp;
    const int ea = (int)(e0 + gidx * 2);     // even
    const int eb = ea + 1;

    const uint4 wv = *(const uint4*)&s_w2h[gl * 4];
    const __half2 zero = u2h(0u);

    // Vectorized index loads: consecutive edges ea, ea+1
    int sa = 0, sc = 0, da = 0, dc = 0;
    bool va_ = (ea < E), vb_ = (eb < E);
    if (va_) {
        if (is64) {
            longlong2 sp = __ldg((const longlong2*)&p64[ea]);
            longlong2 dp = __ldg((const longlong2*)&p64[(size_t)E + ea]);
            sa = (int)sp.x; sc = (int)sp.y;
            da = (int)dp.x; dc = (int)dp.y;
        } else {
            const int* ei = (const int*)ei_raw;
            int2 sp = __ldg((const int2*)&ei[ea]);
            int2 dp = __ldg((const int2*)&ei[(size_t)E + ea]);
            sa = sp.x; sc = sp.y;
            da = dp.x; dc = dp.y;
        }
        sa = min(max(sa, 0), N - 1); da = min(max(da, 0), N - 1);
        sc = min(max(sc, 0), N - 1); dc = min(max(dc, 0), N - 1);
    }

    const u32 gl8 = (u32)(gl * 8);
    uint4 ua4 = make_uint4(0, 0, 0, 0), va4 = ua4, ub4 = ua4, vb4 = ua4;
    if (va_) {
        ua4 = *(const uint4*)&g_UVh[(u32)sa * 256u + gl8];
        va4 = *(const uint4*)&g_UVh[(u32)da * 256u + 128u + gl8];
    }
    if (vb_) {
        ub4 = *(const uint4*)&g_UVh[(u32)sc * 256u + gl8];
        vb4 = *(const uint4*)&g_UVh[(u32)dc * 256u + 128u + gl8];
    }

    float pa, pb;
    {
        __half2 h0 = __hmax2(__hadd2(u2h(ua4.x), u2h(va4.x)), zero);
        __half2 h1 = __hmax2(__hadd2(u2h(ua4.y), u2h(va4.y)), zero);
        __half2 h2 = __hmax2(__hadd2(u2h(ua4.z), u2h(va4.z)), zero);
        __half2 h3 = __hmax2(__hadd2(u2h(ua4.w), u2h(va4.w)), zero);
        __half2 acc0 = __hfma2(h1, u2h(wv.y), __hmul2(h0, u2h(wv.x)));
        __half2 acc1 = __hfma2(h3, u2h(wv.w), __hmul2(h2, u2h(wv.z)));
        float2 f0 = __half22float2(acc0);
        float2 f1 = __half22float2(acc1);
        pa = (f0.x + f0.y) + (f1.x + f1.y);
    }
    {
        __half2 h0 = __hmax2(__hadd2(u2h(ub4.x), u2h(vb4.x)), zero);
        __half2 h1 = __hmax2(__hadd2(u2h(ub4.y), u2h(vb4.y)), zero);
        __half2 h2 = __hmax2(__hadd2(u2h(ub4.z), u2h(vb4.z)), zero);
        __half2 h3 = __hmax2(__hadd2(u2h(ub4.w), u2h(vb4.w)), zero);
        __half2 acc0 = __hfma2(h1, u2h(wv.y), __hmul2(h0, u2h(wv.x)));
        __half2 acc1 = __hfma2(h3, u2h(wv.w), __hmul2(h2, u2h(wv.z)));
        float2 f0 = __half22float2(acc0);
        float2 f1 = __half22float2(acc1);
        pb = (f0.x + f0.y) + (f1.x + f1.y);
    }

#pragma unroll
    for (int off = 8; off > 0; off >>= 1) {
        pa += __shfl_xor_sync(0xffffffffu, pa, off);
        pb += __shfl_xor_sync(0xffffffffu, pb, off);
    }

    if (gl == 0) {
        float b2v = __ldg(b2);
        if (va_) out[ea] = 1.0f / (1.0f + __expf(-(pa + b2v)));
        if (vb_) out[eb] = 1.0f / (1.0f + __expf(-(pb + b2v)));
    }
}

// ---------------------------------------------------------------------------
extern "C" void kernel_launch(void* const* d_in, const int* in_sizes, int n_in,
                              void* d_out, int out_size)
{
    const float* x   = (const float*)d_in[0];
    const void*  ei  = d_in[1];
    const float* W1  = (const float*)d_in[2];
    const float* b1  = (const float*)d_in[3];
    const float* W2  = (const float*)d_in[4];
    const float* b2  = (const float*)d_in[5];
    float* out = (float*)d_out;

    int N = in_sizes[0] / NODE_DIM;   // 100000
    int E = in_sizes[1] / 2;          // 600000

    static int smem_set = 0;
    if (!smem_set) {
        cudaFuncSetAttribute(gemm_mma_kernel,
                             cudaFuncAttributeMaxDynamicSharedMemorySize, SM_TOTAL);
        smem_set = 1;
    }

    gemm_mma_kernel<<<148, 256, SM_TOTAL>>>(x, W1, b1, N);

    int blocks = (E + 31) / 32;
    edge_kernel<<<blocks, 256>>>(ei, W2, b2, out, E, N);
}